// round 3
// baseline (speedup 1.0000x reference)
#include <cuda_runtime.h>
#include <math.h>

#define B_ROWS 8192
#define D_DIM  1024
#define HR_DIM 512
#define HE_DIM 4096
#define HF_DIM 2048

// ---------------- scratch (static __device__, no allocation) ----------------
__device__ float g_H[B_ROWS * HR_DIM];       // router hidden
__device__ float g_Y1[B_ROWS * HE_DIM];      // expert hidden (rows disjoint per expert)
__device__ float g_FUSED[B_ROWS * D_DIM];    // w * selected
__device__ float g_G[B_ROWS * HF_DIM];       // fusion hidden
__device__ float g_w[B_ROWS];                // routing weight of chosen expert
__device__ int   g_hint[B_ROWS];             // emb row (math_op or lang_task)
__device__ int   g_list[2 * B_ROWS];         // compacted row ids per expert
__device__ int   g_cnt[2];

__global__ void reset_kernel() {
    if (threadIdx.x < 2) g_cnt[threadIdx.x] = 0;
}

// ---------------- router head: warp per row ----------------
__global__ void router_head_kernel(const float* __restrict__ Wdom,
                                   const float* __restrict__ bdom,
                                   const float* __restrict__ Wmop,
                                   const float* __restrict__ Wlt) {
    int warp = (blockIdx.x * blockDim.x + threadIdx.x) >> 5;
    int lane = threadIdx.x & 31;
    if (warp >= B_ROWS) return;
    const float* h = g_H + (size_t)warp * HR_DIM;
    float a0 = 0.f, a1 = 0.f;
    float m0 = 0.f, m1 = 0.f, m2 = 0.f, m3 = 0.f;
    float l0 = 0.f, l1 = 0.f, l2 = 0.f, l3 = 0.f;
    for (int i = lane; i < HR_DIM; i += 32) {
        float hv = h[i];
        a0 += hv * Wdom[i * 2 + 0];
        a1 += hv * Wdom[i * 2 + 1];
        m0 += hv * Wmop[i * 4 + 0];
        m1 += hv * Wmop[i * 4 + 1];
        m2 += hv * Wmop[i * 4 + 2];
        m3 += hv * Wmop[i * 4 + 3];
        l0 += hv * Wlt[i * 4 + 0];
        l1 += hv * Wlt[i * 4 + 1];
        l2 += hv * Wlt[i * 4 + 2];
        l3 += hv * Wlt[i * 4 + 3];
    }
#pragma unroll
    for (int off = 16; off > 0; off >>= 1) {
        a0 += __shfl_down_sync(0xffffffffu, a0, off);
        a1 += __shfl_down_sync(0xffffffffu, a1, off);
        m0 += __shfl_down_sync(0xffffffffu, m0, off);
        m1 += __shfl_down_sync(0xffffffffu, m1, off);
        m2 += __shfl_down_sync(0xffffffffu, m2, off);
        m3 += __shfl_down_sync(0xffffffffu, m3, off);
        l0 += __shfl_down_sync(0xffffffffu, l0, off);
        l1 += __shfl_down_sync(0xffffffffu, l1, off);
        l2 += __shfl_down_sync(0xffffffffu, l2, off);
        l3 += __shfl_down_sync(0xffffffffu, l3, off);
    }
    if (lane == 0) {
        a0 += bdom[0];
        a1 += bdom[1];
        int primary = (a1 > a0) ? 1 : 0;  // argmax, first-max wins ties
        float lp = primary ? a1 : a0;
        float lo = primary ? a0 : a1;
        float w = 1.f / (1.f + expf(lo - lp));  // softmax weight of chosen expert
        int mop = 0; float best = m0;
        if (m1 > best) { best = m1; mop = 1; }
        if (m2 > best) { best = m2; mop = 2; }
        if (m3 > best) { best = m3; mop = 3; }
        int lt = 0; best = l0;
        if (l1 > best) { best = l1; lt = 1; }
        if (l2 > best) { best = l2; lt = 2; }
        if (l3 > best) { best = l3; lt = 3; }
        g_w[warp] = w;
        g_hint[warp] = primary ? lt : mop;
        int pos = atomicAdd(&g_cnt[primary], 1);
        g_list[primary * B_ROWS + pos] = warp;
    }
}

// ---------------- fp32 GEMM: C = epilogue(A @ W + bias) ----------------
// BM=BN=128, BK=8, 256 threads, 8x8 microtile.
// GATHER: row ids via rowlist (count via cntPtr), A rows gathered, C rows scattered.
// ADD_EMB: A row += emb[g_hint[row]]
// RELU / SCALE (w[row]*(dot+bias)) / RESID (+= resid[row])
template <bool GATHER, bool ADD_EMB, bool RELU, bool SCALE, bool RESID>
__global__ __launch_bounds__(256, 2) void gemm128_kernel(
    const float* __restrict__ A, const float* __restrict__ W,
    const float* __restrict__ bias, float* __restrict__ C,
    const float* __restrict__ resid, int N, int K,
    const int* __restrict__ rowlist, const int* __restrict__ cntPtr,
    const float* __restrict__ emb) {
    const int BM = 128, BN = 128, BK = 8;
    __shared__ float As[BK][BM];
    __shared__ float Bs[BK][BN];
    __shared__ int   rmap[BM];
    __shared__ float rsc[BM];

    int tid = threadIdx.x;
    int tile_m = blockIdx.y * BM;
    int tile_n = blockIdx.x * BN;

    int cnt = B_ROWS;
    if (GATHER) {
        cnt = *cntPtr;
        if (tile_m >= cnt) return;
    }
    if (tid < BM) {
        int m = tile_m + tid;
        int r;
        if (GATHER) r = (m < cnt) ? rowlist[m] : -1;
        else        r = m;
        rmap[tid] = r;
        if (SCALE) rsc[tid] = (r >= 0) ? g_w[r] : 0.f;
    }
    __syncthreads();

    int tx = tid & 15;   // col group
    int ty = tid >> 4;   // row group
    int arow = tid >> 1;
    int akq = (tid & 1) * 4;
    int bkr = tid >> 5;
    int bc = (tid & 31) * 4;

    int r_a = rmap[arow];
    const float* aptr = (r_a >= 0) ? (A + (size_t)r_a * K + akq) : nullptr;
    const float* eptr = nullptr;
    if (ADD_EMB && r_a >= 0) eptr = emb + (size_t)g_hint[r_a] * K + akq;

    float acc[8][8];
#pragma unroll
    for (int i = 0; i < 8; i++)
#pragma unroll
        for (int j = 0; j < 8; j++) acc[i][j] = 0.f;

    for (int k0 = 0; k0 < K; k0 += BK) {
        float4 av = make_float4(0.f, 0.f, 0.f, 0.f);
        if (r_a >= 0) {
            av = *reinterpret_cast<const float4*>(aptr + k0);
            if (ADD_EMB) {
                float4 ev = *reinterpret_cast<const float4*>(eptr + k0);
                av.x += ev.x; av.y += ev.y; av.z += ev.z; av.w += ev.w;
            }
        }
        float4 bv = *reinterpret_cast<const float4*>(W + (size_t)(k0 + bkr) * N + tile_n + bc);
        __syncthreads();
        As[akq + 0][arow] = av.x;
        As[akq + 1][arow] = av.y;
        As[akq + 2][arow] = av.z;
        As[akq + 3][arow] = av.w;
        *reinterpret_cast<float4*>(&Bs[bkr][bc]) = bv;
        __syncthreads();
#pragma unroll
        for (int kk = 0; kk < BK; kk++) {
            float4 a0v = *reinterpret_cast<const float4*>(&As[kk][ty * 8]);
            float4 a1v = *reinterpret_cast<const float4*>(&As[kk][ty * 8 + 4]);
            float4 b0v = *reinterpret_cast<const float4*>(&Bs[kk][tx * 8]);
            float4 b1v = *reinterpret_cast<const float4*>(&Bs[kk][tx * 8 + 4]);
            float aa[8] = {a0v.x, a0v.y, a0v.z, a0v.w, a1v.x, a1v.y, a1v.z, a1v.w};
            float bb[8] = {b0v.x, b0v.y, b0v.z, b0v.w, b1v.x, b1v.y, b1v.z, b1v.w};
#pragma unroll
            for (int i = 0; i < 8; i++)
#pragma unroll
                for (int j = 0; j < 8; j++) acc[i][j] += aa[i] * bb[j];
        }
    }

    // epilogue
    float bfrag[8];
#pragma unroll
    for (int j = 0; j < 8; j++) bfrag[j] = bias[tile_n + tx * 8 + j];
#pragma unroll
    for (int i = 0; i < 8; i++) {
        int r = rmap[ty * 8 + i];
        if (r < 0) continue;
        float sc = SCALE ? rsc[ty * 8 + i] : 1.f;
        size_t off = (size_t)r * N + tile_n + tx * 8;
        float v[8];
#pragma unroll
        for (int j = 0; j < 8; j++) {
            float t = acc[i][j] + bfrag[j];
            if (RELU) t = fmaxf(t, 0.f);
            if (SCALE) t *= sc;
            v[j] = t;
        }
        if (RESID) {
            float4 r0 = *reinterpret_cast<const float4*>(resid + off);
            float4 r1 = *reinterpret_cast<const float4*>(resid + off + 4);
            v[0] += r0.x; v[1] += r0.y; v[2] += r0.z; v[3] += r0.w;
            v[4] += r1.x; v[5] += r1.y; v[6] += r1.z; v[7] += r1.w;
        }
        *reinterpret_cast<float4*>(C + off)     = make_float4(v[0], v[1], v[2], v[3]);
        *reinterpret_cast<float4*>(C + off + 4) = make_float4(v[4], v[5], v[6], v[7]);
    }
}

// ---------------- launch ----------------
extern "C" void kernel_launch(void* const* d_in, const int* in_sizes, int n_in,
                              void* d_out, int out_size) {
    const float* x       = (const float*)d_in[0];
    const float* W_r1    = (const float*)d_in[1];
    const float* b_r1    = (const float*)d_in[2];
    const float* W_dom   = (const float*)d_in[3];
    const float* b_dom   = (const float*)d_in[4];
    const float* W_mop   = (const float*)d_in[5];
    const float* W_lt    = (const float*)d_in[6];
    const float* op_emb  = (const float*)d_in[7];
    const float* W_m1    = (const float*)d_in[8];
    const float* b_m1    = (const float*)d_in[9];
    const float* W_m2    = (const float*)d_in[10];
    const float* b_m2    = (const float*)d_in[11];
    const float* task_emb= (const float*)d_in[12];
    const float* W_l1    = (const float*)d_in[13];
    const float* b_l1    = (const float*)d_in[14];
    const float* W_l2    = (const float*)d_in[15];
    const float* b_l2    = (const float*)d_in[16];
    const float* W_f1    = (const float*)d_in[17];
    const float* b_f1    = (const float*)d_in[18];
    const float* W_f2    = (const float*)d_in[19];
    const float* b_f2    = (const float*)d_in[20];
    float* out = (float*)d_out;

    float *H, *Y1, *FUSED, *G;
    int *list, *cnt;
    cudaGetSymbolAddress((void**)&H, g_H);
    cudaGetSymbolAddress((void**)&Y1, g_Y1);
    cudaGetSymbolAddress((void**)&FUSED, g_FUSED);
    cudaGetSymbolAddress((void**)&G, g_G);
    cudaGetSymbolAddress((void**)&list, g_list);
    cudaGetSymbolAddress((void**)&cnt, g_cnt);

    dim3 blk(256);
    int mtiles = B_ROWS / 128;

    reset_kernel<<<1, 32>>>();

    // router GEMM: H = relu(x @ W_r1 + b_r1)
    gemm128_kernel<false, false, true, false, false>
        <<<dim3(HR_DIM / 128, mtiles), blk>>>(x, W_r1, b_r1, H, nullptr,
                                              HR_DIM, D_DIM, nullptr, nullptr, nullptr);
    // router head + compaction
    router_head_kernel<<<B_ROWS / 8, 256>>>(W_dom, b_dom, W_mop, W_lt);

    // expert pass 1: Y1[r] = relu((x[r] + emb[hint[r]]) @ W1 + b1)
    gemm128_kernel<true, true, true, false, false>
        <<<dim3(HE_DIM / 128, mtiles), blk>>>(x, W_m1, b_m1, Y1, nullptr,
                                              HE_DIM, D_DIM, list, cnt, op_emb);
    gemm128_kernel<true, true, true, false, false>
        <<<dim3(HE_DIM / 128, mtiles), blk>>>(x, W_l1, b_l1, Y1, nullptr,
                                              HE_DIM, D_DIM, list + B_ROWS, cnt + 1, task_emb);

    // expert pass 2: FUSED[r] = w[r] * (Y1[r] @ W2 + b2)
    gemm128_kernel<true, false, false, true, false>
        <<<dim3(D_DIM / 128, mtiles), blk>>>(Y1, W_m2, b_m2, FUSED, nullptr,
                                             D_DIM, HE_DIM, list, cnt, nullptr);
    gemm128_kernel<true, false, false, true, false>
        <<<dim3(D_DIM / 128, mtiles), blk>>>(Y1, W_l2, b_l2, FUSED, nullptr,
                                             D_DIM, HE_DIM, list + B_ROWS, cnt + 1, nullptr);

    // fusion: G = relu(FUSED @ W_f1 + b_f1)
    gemm128_kernel<false, false, true, false, false>
        <<<dim3(HF_DIM / 128, mtiles), blk>>>(FUSED, W_f1, b_f1, G, nullptr,
                                              HF_DIM, D_DIM, nullptr, nullptr, nullptr);
    // final: out = FUSED + G @ W_f2 + b_f2
    gemm128_kernel<false, false, false, false, true>
        <<<dim3(D_DIM / 128, mtiles), blk>>>(G, W_f2, b_f2, out, FUSED,
                                             D_DIM, HF_DIM, nullptr, nullptr, nullptr);
}

// round 5
// speedup vs baseline: 2.8881x; 2.8881x over previous
#include <cuda_runtime.h>
#include <cuda_bf16.h>
#include <stdint.h>
#include <math.h>

#define B_ROWS 8192
#define ROWS_PAD 8448
#define D_DIM 1024
#define HR_DIM 512
#define HE_DIM 4096
#define HF_DIM 2048

// ---------------- PTX helpers (base sm_103-safe: cp.async / ldmatrix / mma.sync) ----
__device__ __forceinline__ uint32_t smem_u32(const void* p) {
    uint32_t a;
    asm("{ .reg .u64 t; cvta.to.shared.u64 t, %1; cvt.u32.u64 %0, t; }" : "=r"(a) : "l"(p));
    return a;
}
__device__ __forceinline__ void cp16(uint32_t dst, const void* src) {
    asm volatile("cp.async.cg.shared.global [%0], [%1], 16;" :: "r"(dst), "l"(src));
}
#define CP_COMMIT asm volatile("cp.async.commit_group;" ::: "memory")
#define CP_WAIT1  asm volatile("cp.async.wait_group 1;" ::: "memory")

__device__ __forceinline__ void ldsm4(uint32_t& r0, uint32_t& r1, uint32_t& r2, uint32_t& r3,
                                      uint32_t a) {
    asm volatile("ldmatrix.sync.aligned.m8n8.x4.shared.b16 {%0,%1,%2,%3}, [%4];"
                 : "=r"(r0), "=r"(r1), "=r"(r2), "=r"(r3) : "r"(a));
}
__device__ __forceinline__ void mma16816(float (&d)[4], const uint32_t (&a)[4],
                                         uint32_t b0, uint32_t b1) {
    asm volatile(
        "mma.sync.aligned.m16n8k16.row.col.f32.bf16.bf16.f32 "
        "{%0,%1,%2,%3}, {%4,%5,%6,%7}, {%8,%9}, {%0,%1,%2,%3};"
        : "+f"(d[0]), "+f"(d[1]), "+f"(d[2]), "+f"(d[3])
        : "r"(a[0]), "r"(a[1]), "r"(a[2]), "r"(a[3]), "r"(b0), "r"(b1));
}
__device__ __forceinline__ void split2(float v, __nv_bfloat16& h, __nv_bfloat16& l) {
    h = __float2bfloat16(v);
    l = __float2bfloat16(v - __bfloat162float(h));
}

// ---------------- scratch ----------------
#define SZ_R1 (HR_DIM * D_DIM)
#define SZ_E1 (HE_DIM * D_DIM)
#define SZ_F1 (HF_DIM * D_DIM)
#define WOFF_R1 0
#define WOFF_M1 (WOFF_R1 + SZ_R1)
#define WOFF_L1 (WOFF_M1 + SZ_E1)
#define WOFF_M2 (WOFF_L1 + SZ_E1)
#define WOFF_L2 (WOFF_M2 + SZ_E1)
#define WOFF_F1 (WOFF_L2 + SZ_E1)
#define WOFF_F2 (WOFF_F1 + SZ_F1)
#define WPOOL_SZ (WOFF_F2 + SZ_F1)

__device__ __align__(256) __nv_bfloat16 g_whi[WPOOL_SZ];
__device__ __align__(256) __nv_bfloat16 g_wlo[WPOOL_SZ];
__device__ __align__(256) __nv_bfloat16 g_xhi[B_ROWS * D_DIM];
__device__ __align__(256) __nv_bfloat16 g_xlo[B_ROWS * D_DIM];
__device__ __align__(256) float g_H[B_ROWS * HR_DIM];
__device__ __align__(256) __nv_bfloat16 g_xehi[ROWS_PAD * D_DIM];
__device__ __align__(256) __nv_bfloat16 g_xelo[ROWS_PAD * D_DIM];
__device__ __align__(256) __nv_bfloat16 g_y1hi[(size_t)ROWS_PAD * HE_DIM];
__device__ __align__(256) __nv_bfloat16 g_y1lo[(size_t)ROWS_PAD * HE_DIM];
__device__ __align__(256) float g_Ff[B_ROWS * D_DIM];
__device__ __align__(256) __nv_bfloat16 g_fhi[B_ROWS * D_DIM];
__device__ __align__(256) __nv_bfloat16 g_flo[B_ROWS * D_DIM];
__device__ __align__(256) __nv_bfloat16 g_ghi[B_ROWS * HF_DIM];
__device__ __align__(256) __nv_bfloat16 g_glo[B_ROWS * HF_DIM];
__device__ float g_w[B_ROWS];
__device__ int g_hint[B_ROWS];
__device__ int g_list[2 * B_ROWS];
__device__ int g_cnt[2];
__device__ int g_A0;
__device__ int g_cmap[ROWS_PAD];

__global__ void reset_kernel() {
    if (threadIdx.x < 2) g_cnt[threadIdx.x] = 0;
}
__global__ void calca0_kernel() { g_A0 = ((g_cnt[0] + 127) >> 7) << 7; }

// W [K,N] fp32 -> hi/lo bf16 [N,K] K-major
__global__ void wconv_kernel(const float* __restrict__ W, __nv_bfloat16* __restrict__ hi,
                             __nv_bfloat16* __restrict__ lo, int K, int N) {
    __shared__ float t[32][33];
    int k0 = blockIdx.y * 32, n0 = blockIdx.x * 32;
    int tx = threadIdx.x, ty = threadIdx.y;
#pragma unroll
    for (int j = 0; j < 4; j++)
        t[ty + j * 8][tx] = W[(size_t)(k0 + ty + j * 8) * N + n0 + tx];
    __syncthreads();
#pragma unroll
    for (int j = 0; j < 4; j++) {
        int n = n0 + ty + j * 8, k = k0 + tx;
        __nv_bfloat16 h, l;
        split2(t[tx][ty + j * 8], h, l);
        hi[(size_t)n * K + k] = h;
        lo[(size_t)n * K + k] = l;
    }
}

__global__ void xconv_kernel(const float* __restrict__ x) {
    size_t i = ((size_t)blockIdx.x * blockDim.x + threadIdx.x) * 4;
    float4 v = *(const float4*)(x + i);
    __nv_bfloat16 h, l;
    split2(v.x, h, l); g_xhi[i] = h;     g_xlo[i] = l;
    split2(v.y, h, l); g_xhi[i + 1] = h; g_xlo[i + 1] = l;
    split2(v.z, h, l); g_xhi[i + 2] = h; g_xlo[i + 2] = l;
    split2(v.w, h, l); g_xhi[i + 3] = h; g_xlo[i + 3] = l;
}

__global__ void router_head_kernel(const float* __restrict__ Wdom, const float* __restrict__ bdom,
                                   const float* __restrict__ Wmop, const float* __restrict__ Wlt) {
    int warp = (blockIdx.x * blockDim.x + threadIdx.x) >> 5;
    int lane = threadIdx.x & 31;
    if (warp >= B_ROWS) return;
    const float* h = g_H + (size_t)warp * HR_DIM;
    float a0 = 0, a1 = 0, m0 = 0, m1 = 0, m2 = 0, m3 = 0, l0 = 0, l1 = 0, l2 = 0, l3 = 0;
    for (int i = lane; i < HR_DIM; i += 32) {
        float hv = h[i];
        a0 += hv * Wdom[i * 2];     a1 += hv * Wdom[i * 2 + 1];
        m0 += hv * Wmop[i * 4];     m1 += hv * Wmop[i * 4 + 1];
        m2 += hv * Wmop[i * 4 + 2]; m3 += hv * Wmop[i * 4 + 3];
        l0 += hv * Wlt[i * 4];      l1 += hv * Wlt[i * 4 + 1];
        l2 += hv * Wlt[i * 4 + 2];  l3 += hv * Wlt[i * 4 + 3];
    }
#pragma unroll
    for (int o = 16; o > 0; o >>= 1) {
        a0 += __shfl_down_sync(~0u, a0, o); a1 += __shfl_down_sync(~0u, a1, o);
        m0 += __shfl_down_sync(~0u, m0, o); m1 += __shfl_down_sync(~0u, m1, o);
        m2 += __shfl_down_sync(~0u, m2, o); m3 += __shfl_down_sync(~0u, m3, o);
        l0 += __shfl_down_sync(~0u, l0, o); l1 += __shfl_down_sync(~0u, l1, o);
        l2 += __shfl_down_sync(~0u, l2, o); l3 += __shfl_down_sync(~0u, l3, o);
    }
    if (lane == 0) {
        a0 += bdom[0]; a1 += bdom[1];
        int primary = (a1 > a0) ? 1 : 0;
        float w = 1.f / (1.f + expf((primary ? a0 : a1) - (primary ? a1 : a0)));
        int mop = 0; float b = m0;
        if (m1 > b) { b = m1; mop = 1; }
        if (m2 > b) { b = m2; mop = 2; }
        if (m3 > b) { b = m3; mop = 3; }
        int lt = 0; b = l0;
        if (l1 > b) { b = l1; lt = 1; }
        if (l2 > b) { b = l2; lt = 2; }
        if (l3 > b) { b = l3; lt = 3; }
        g_w[warp] = w;
        g_hint[warp] = primary ? lt : mop;
        int pos = atomicAdd(&g_cnt[primary], 1);
        g_list[primary * B_ROWS + pos] = warp;
    }
}

// compact gather: slot b <- split(x[orig] + emb[hint[orig]])
__global__ void gather_kernel(const float* __restrict__ x, const float* __restrict__ op_emb,
                              const float* __restrict__ task_emb) {
    int bidx = blockIdx.x;
    int c0 = g_cnt[0], c1 = g_cnt[1], A0 = g_A0;
    int orig = -1;
    const float* er = nullptr;
    if (bidx < c0) {
        orig = g_list[bidx];
        er = op_emb + (size_t)g_hint[orig] * D_DIM;
    } else if (bidx >= A0 && bidx < A0 + c1) {
        orig = g_list[B_ROWS + bidx - A0];
        er = task_emb + (size_t)g_hint[orig] * D_DIM;
    }
    if (threadIdx.x == 0) g_cmap[bidx] = orig;
    if (orig < 0) return;
    const float* xr = x + (size_t)orig * D_DIM;
    size_t ob = (size_t)bidx * D_DIM;
    for (int i = threadIdx.x * 4; i < D_DIM; i += 512) {
        float4 xv = *(const float4*)(xr + i);
        float4 ev = *(const float4*)(er + i);
        float s[4] = {xv.x + ev.x, xv.y + ev.y, xv.z + ev.z, xv.w + ev.w};
#pragma unroll
        for (int j = 0; j < 4; j++) {
            __nv_bfloat16 h, l;
            split2(s[j], h, l);
            g_xehi[ob + i + j] = h;
            g_xelo[ob + i + j] = l;
        }
    }
}

// ---------------- HMMA bf16x3 GEMM: 128x128 tile, BK=32, 2-stage cp.async ----------
// SMEM row (128B) = [hi 64B | lo 64B], swizzle: loc = r*128 + (byteoff ^ ((r&7)<<4))
#define STAGE_BYTES 32768
#define DYN_SMEM (2 * STAGE_BYTES + 128)

template <bool RELU, bool SCAT, bool RESID, bool WF32, bool WBF, bool LOLO>
__global__ void __launch_bounds__(256, 1) mm_hmma(
    const __nv_bfloat16* __restrict__ Ahi, const __nv_bfloat16* __restrict__ Alo,
    const __nv_bfloat16* __restrict__ Bhi, const __nv_bfloat16* __restrict__ Blo,
    const float* __restrict__ bias, float* __restrict__ Cf,
    __nv_bfloat16* __restrict__ Chi, __nv_bfloat16* __restrict__ Clo,
    const float* __restrict__ resid, int N, int K,
    const int* __restrict__ mbase, const int* __restrict__ mcount) {
    if (mcount && (int)blockIdx.y * 128 >= *mcount) return;
    const int m0 = (mbase ? *mbase : 0) + blockIdx.y * 128;
    const int n0 = blockIdx.x * 128;
    const int tid = threadIdx.x;
    const int lane = tid & 31, wid = tid >> 5;
    const int wm = wid & 3, wn = wid >> 2;

    extern __shared__ char sm_raw[];
    char* sm = (char*)(((uintptr_t)sm_raw + 127) & ~(uintptr_t)127);
    const uint32_t sbase = smem_u32(sm);

    float acc[2][8][4];
#pragma unroll
    for (int a = 0; a < 2; a++)
#pragma unroll
        for (int b = 0; b < 8; b++)
#pragma unroll
            for (int c = 0; c < 4; c++) acc[a][b][c] = 0.f;

    const int niter = K >> 5;

    auto issue = [&](int it) {
        const int slot = it & 1;
        const int k0 = it << 5;
        const uint32_t as = sbase + slot * STAGE_BYTES;
        const uint32_t bs = as + 16384;
#pragma unroll
        for (int rep = 0; rep < 4; rep++) {
            int c = rep * 256 + tid;
            int r = c >> 3, j8 = c & 7;
            int j = j8 & 3;
            uint32_t loc = (uint32_t)(r * 128 + ((j8 * 16) ^ ((r & 7) << 4)));
            const __nv_bfloat16* src =
                ((j8 >> 2) ? Alo : Ahi) + (size_t)(m0 + r) * K + k0 + j * 8;
            cp16(as + loc, src);
        }
#pragma unroll
        for (int rep = 0; rep < 4; rep++) {
            int c = rep * 256 + tid;
            int r = c >> 3, j8 = c & 7;
            int j = j8 & 3;
            uint32_t loc = (uint32_t)(r * 128 + ((j8 * 16) ^ ((r & 7) << 4)));
            const __nv_bfloat16* src =
                ((j8 >> 2) ? Blo : Bhi) + (size_t)(n0 + r) * K + k0 + j * 8;
            cp16(bs + loc, src);
        }
    };

    auto compute = [&](int slot) {
        const uint32_t as = sbase + slot * STAGE_BYTES;
        const uint32_t bs = as + 16384;
#pragma unroll
        for (int ks = 0; ks < 2; ks++) {
            const int kb = ks * 32;
            uint32_t ah[2][4], al[2][4];
#pragma unroll
            for (int mt = 0; mt < 2; mt++) {
                int r = wm * 32 + mt * 16 + (lane & 15);
                int sw = (r & 7) << 4;
                uint32_t rb = as + r * 128;
                int bo = kb + ((lane >> 4) << 4);
                ldsm4(ah[mt][0], ah[mt][1], ah[mt][2], ah[mt][3], rb + (uint32_t)(bo ^ sw));
                ldsm4(al[mt][0], al[mt][1], al[mt][2], al[mt][3],
                      rb + (uint32_t)((bo + 64) ^ sw));
            }
#pragma unroll
            for (int np = 0; np < 4; np++) {
                int r = wn * 64 + np * 16 + (lane & 7) + ((lane >> 4) << 3);
                int sw = (r & 7) << 4;
                uint32_t rb = bs + r * 128;
                int bo = kb + (((lane >> 3) & 1) << 4);
                uint32_t bh[4], bl[4];
                ldsm4(bh[0], bh[1], bh[2], bh[3], rb + (uint32_t)(bo ^ sw));
                ldsm4(bl[0], bl[1], bl[2], bl[3], rb + (uint32_t)((bo + 64) ^ sw));
#pragma unroll
                for (int mt = 0; mt < 2; mt++) {
                    mma16816(acc[mt][np * 2],     ah[mt], bh[0], bh[1]);
                    mma16816(acc[mt][np * 2 + 1], ah[mt], bh[2], bh[3]);
                    mma16816(acc[mt][np * 2],     ah[mt], bl[0], bl[1]);
                    mma16816(acc[mt][np * 2 + 1], ah[mt], bl[2], bl[3]);
                    mma16816(acc[mt][np * 2],     al[mt], bh[0], bh[1]);
                    mma16816(acc[mt][np * 2 + 1], al[mt], bh[2], bh[3]);
                    if (LOLO) {
                        mma16816(acc[mt][np * 2],     al[mt], bl[0], bl[1]);
                        mma16816(acc[mt][np * 2 + 1], al[mt], bl[2], bl[3]);
                    }
                }
            }
        }
    };

    issue(0); CP_COMMIT;
    issue(1); CP_COMMIT;
    for (int i = 0; i < niter; i++) {
        CP_WAIT1;
        __syncthreads();
        compute(i & 1);
        __syncthreads();
        if (i + 2 < niter) issue(i + 2);
        CP_COMMIT;
    }

    // ---- epilogue ----
    const int tg = lane & 3, g = lane >> 2;
#pragma unroll
    for (int mt = 0; mt < 2; mt++) {
#pragma unroll
        for (int h2 = 0; h2 < 2; h2++) {
            int row = m0 + wm * 32 + mt * 16 + g + h2 * 8;
            int orig = row;
            float wsc = 1.f;
            bool valid = true;
            if (SCAT) {
                orig = g_cmap[row];
                valid = orig >= 0;
                wsc = valid ? g_w[orig] : 0.f;
            }
            if (!valid) continue;
            size_t rowoff = (size_t)orig * N;
#pragma unroll
            for (int nt = 0; nt < 8; nt++) {
                int col = n0 + wn * 64 + nt * 8 + tg * 2;
                float v0 = acc[mt][nt][h2 * 2]     + bias[col];
                float v1 = acc[mt][nt][h2 * 2 + 1] + bias[col + 1];
                if (RELU) { v0 = fmaxf(v0, 0.f); v1 = fmaxf(v1, 0.f); }
                if (SCAT) { v0 *= wsc; v1 *= wsc; }
                if (RESID) {
                    float2 rv = *(const float2*)(resid + rowoff + col);
                    v0 += rv.x; v1 += rv.y;
                }
                if (WF32) {
                    float2 o; o.x = v0; o.y = v1;
                    *(float2*)(Cf + rowoff + col) = o;
                }
                if (WBF) {
                    __nv_bfloat16 h0, l0, h1, l1;
                    split2(v0, h0, l0);
                    split2(v1, h1, l1);
                    __nv_bfloat162 hh; hh.x = h0; hh.y = h1;
                    __nv_bfloat162 ll; ll.x = l0; ll.y = l1;
                    *(__nv_bfloat162*)(Chi + rowoff + col) = hh;
                    *(__nv_bfloat162*)(Clo + rowoff + col) = ll;
                }
            }
        }
    }
}

// ---------------- launch ----------------
extern "C" void kernel_launch(void* const* d_in, const int* in_sizes, int n_in,
                              void* d_out, int out_size) {
    const float* x        = (const float*)d_in[0];
    const float* W_r1     = (const float*)d_in[1];
    const float* b_r1     = (const float*)d_in[2];
    const float* W_dom    = (const float*)d_in[3];
    const float* b_dom    = (const float*)d_in[4];
    const float* W_mop    = (const float*)d_in[5];
    const float* W_lt     = (const float*)d_in[6];
    const float* op_emb   = (const float*)d_in[7];
    const float* W_m1     = (const float*)d_in[8];
    const float* b_m1     = (const float*)d_in[9];
    const float* W_m2     = (const float*)d_in[10];
    const float* b_m2     = (const float*)d_in[11];
    const float* task_emb = (const float*)d_in[12];
    const float* W_l1     = (const float*)d_in[13];
    const float* b_l1     = (const float*)d_in[14];
    const float* W_l2     = (const float*)d_in[15];
    const float* b_l2     = (const float*)d_in[16];
    const float* W_f1     = (const float*)d_in[17];
    const float* b_f1     = (const float*)d_in[18];
    const float* W_f2     = (const float*)d_in[19];
    const float* b_f2     = (const float*)d_in[20];
    float* out = (float*)d_out;

    __nv_bfloat16 *whi, *wlo, *xhi, *xlo, *xehi, *xelo, *y1hi, *y1lo, *fhi, *flo, *ghi, *glo;
    float *H, *Ff;
    int *cnt, *A0;
    cudaGetSymbolAddress((void**)&whi, g_whi);
    cudaGetSymbolAddress((void**)&wlo, g_wlo);
    cudaGetSymbolAddress((void**)&xhi, g_xhi);
    cudaGetSymbolAddress((void**)&xlo, g_xlo);
    cudaGetSymbolAddress((void**)&xehi, g_xehi);
    cudaGetSymbolAddress((void**)&xelo, g_xelo);
    cudaGetSymbolAddress((void**)&y1hi, g_y1hi);
    cudaGetSymbolAddress((void**)&y1lo, g_y1lo);
    cudaGetSymbolAddress((void**)&fhi, g_fhi);
    cudaGetSymbolAddress((void**)&flo, g_flo);
    cudaGetSymbolAddress((void**)&ghi, g_ghi);
    cudaGetSymbolAddress((void**)&glo, g_glo);
    cudaGetSymbolAddress((void**)&H, g_H);
    cudaGetSymbolAddress((void**)&Ff, g_Ff);
    cudaGetSymbolAddress((void**)&cnt, g_cnt);
    cudaGetSymbolAddress((void**)&A0, g_A0);

    cudaFuncSetAttribute((const void*)mm_hmma<true, false, false, true, false, true>,
                         cudaFuncAttributeMaxDynamicSharedMemorySize, DYN_SMEM);
    cudaFuncSetAttribute((const void*)mm_hmma<true, false, false, false, true, false>,
                         cudaFuncAttributeMaxDynamicSharedMemorySize, DYN_SMEM);
    cudaFuncSetAttribute((const void*)mm_hmma<false, true, false, true, true, false>,
                         cudaFuncAttributeMaxDynamicSharedMemorySize, DYN_SMEM);
    cudaFuncSetAttribute((const void*)mm_hmma<false, false, true, true, false, false>,
                         cudaFuncAttributeMaxDynamicSharedMemorySize, DYN_SMEM);

    dim3 blk(256);
    dim3 wblk(32, 8);
    int mtiles = B_ROWS / 128;

    reset_kernel<<<1, 32>>>();
    wconv_kernel<<<dim3(HR_DIM / 32, D_DIM / 32), wblk>>>(W_r1, whi + WOFF_R1, wlo + WOFF_R1, D_DIM, HR_DIM);
    wconv_kernel<<<dim3(HE_DIM / 32, D_DIM / 32), wblk>>>(W_m1, whi + WOFF_M1, wlo + WOFF_M1, D_DIM, HE_DIM);
    wconv_kernel<<<dim3(HE_DIM / 32, D_DIM / 32), wblk>>>(W_l1, whi + WOFF_L1, wlo + WOFF_L1, D_DIM, HE_DIM);
    wconv_kernel<<<dim3(D_DIM / 32, HE_DIM / 32), wblk>>>(W_m2, whi + WOFF_M2, wlo + WOFF_M2, HE_DIM, D_DIM);
    wconv_kernel<<<dim3(D_DIM / 32, HE_DIM / 32), wblk>>>(W_l2, whi + WOFF_L2, wlo + WOFF_L2, HE_DIM, D_DIM);
    wconv_kernel<<<dim3(HF_DIM / 32, D_DIM / 32), wblk>>>(W_f1, whi + WOFF_F1, wlo + WOFF_F1, D_DIM, HF_DIM);
    wconv_kernel<<<dim3(D_DIM / 32, HF_DIM / 32), wblk>>>(W_f2, whi + WOFF_F2, wlo + WOFF_F2, HF_DIM, D_DIM);
    xconv_kernel<<<B_ROWS * D_DIM / 1024, 256>>>(x);

    // router: H = relu(x @ W_r1 + b_r1)   (bf16x4 — exact enough that argmaxes never flip)
    mm_hmma<true, false, false, true, false, true><<<dim3(HR_DIM / 128, mtiles), blk, DYN_SMEM>>>(
        xhi, xlo, whi + WOFF_R1, wlo + WOFF_R1, b_r1, H, nullptr, nullptr, nullptr,
        HR_DIM, D_DIM, nullptr, nullptr);
    router_head_kernel<<<B_ROWS / 8, 256>>>(W_dom, b_dom, W_mop, W_lt);
    calca0_kernel<<<1, 1>>>();
    gather_kernel<<<ROWS_PAD, 128>>>(x, op_emb, task_emb);

    // expert layer 1 (compact dense): Y1 = relu(XE @ W1 + b1), emit hi/lo bf16
    mm_hmma<true, false, false, false, true, false><<<dim3(HE_DIM / 128, mtiles), blk, DYN_SMEM>>>(
        xehi, xelo, whi + WOFF_M1, wlo + WOFF_M1, b_m1, nullptr, y1hi, y1lo, nullptr,
        HE_DIM, D_DIM, nullptr, cnt);
    mm_hmma<true, false, false, false, true, false><<<dim3(HE_DIM / 128, mtiles), blk, DYN_SMEM>>>(
        xehi, xelo, whi + WOFF_L1, wlo + WOFF_L1, b_l1, nullptr, y1hi, y1lo, nullptr,
        HE_DIM, D_DIM, A0, cnt + 1);
    // expert layer 2: FUSED[orig] = w * (Y1 @ W2 + b2), scatter, fp32 + hi/lo bf16
    mm_hmma<false, true, false, true, true, false><<<dim3(D_DIM / 128, mtiles), blk, DYN_SMEM>>>(
        y1hi, y1lo, whi + WOFF_M2, wlo + WOFF_M2, b_m2, Ff, fhi, flo, nullptr,
        D_DIM, HE_DIM, nullptr, cnt);
    mm_hmma<false, true, false, true, true, false><<<dim3(D_DIM / 128, mtiles), blk, DYN_SMEM>>>(
        y1hi, y1lo, whi + WOFF_L2, wlo + WOFF_L2, b_l2, Ff, fhi, flo, nullptr,
        D_DIM, HE_DIM, A0, cnt + 1);
    // fusion layer 1: G = relu(FUSED @ W_f1 + b_f1)
    mm_hmma<true, false, false, false, true, false><<<dim3(HF_DIM / 128, mtiles), blk, DYN_SMEM>>>(
        fhi, flo, whi + WOFF_F1, wlo + WOFF_F1, b_f1, nullptr, ghi, glo, nullptr,
        HF_DIM, D_DIM, nullptr, nullptr);
    // fusion layer 2: out = FUSED + G @ W_f2 + b_f2
    mm_hmma<false, false, true, true, false, false><<<dim3(D_DIM / 128, mtiles), blk, DYN_SMEM>>>(
        ghi, glo, whi + WOFF_F2, wlo + WOFF_F2, b_f2, out, nullptr, nullptr, Ff,
        D_DIM, HF_DIM, nullptr, nullptr);
}

// round 7
// speedup vs baseline: 2.9037x; 1.0054x over previous
#include <cuda_runtime.h>
#include <cuda_bf16.h>
#include <stdint.h>
#include <math.h>

#define B_ROWS 8192
#define ROWS_PAD 8448
#define D_DIM 1024
#define HR_DIM 512
#define HE_DIM 4096
#define HF_DIM 2048

// ---------------- PTX helpers (base sm_103-safe) ----------------
__device__ __forceinline__ uint32_t smem_u32(const void* p) {
    uint32_t a;
    asm("{ .reg .u64 t; cvta.to.shared.u64 t, %1; cvt.u32.u64 %0, t; }" : "=r"(a) : "l"(p));
    return a;
}
__device__ __forceinline__ void cp16(uint32_t dst, const void* src) {
    asm volatile("cp.async.cg.shared.global [%0], [%1], 16;" :: "r"(dst), "l"(src));
}
#define CP_COMMIT asm volatile("cp.async.commit_group;" ::: "memory")
#define CP_WAIT2  asm volatile("cp.async.wait_group 2;" ::: "memory")

__device__ __forceinline__ void ldsm4(uint32_t& r0, uint32_t& r1, uint32_t& r2, uint32_t& r3,
                                      uint32_t a) {
    asm volatile("ldmatrix.sync.aligned.m8n8.x4.shared.b16 {%0,%1,%2,%3}, [%4];"
                 : "=r"(r0), "=r"(r1), "=r"(r2), "=r"(r3) : "r"(a));
}
__device__ __forceinline__ void mma16816(float (&d)[4], const uint32_t (&a)[4],
                                         uint32_t b0, uint32_t b1) {
    asm volatile(
        "mma.sync.aligned.m16n8k16.row.col.f32.bf16.bf16.f32 "
        "{%0,%1,%2,%3}, {%4,%5,%6,%7}, {%8,%9}, {%0,%1,%2,%3};"
        : "+f"(d[0]), "+f"(d[1]), "+f"(d[2]), "+f"(d[3])
        : "r"(a[0]), "r"(a[1]), "r"(a[2]), "r"(a[3]), "r"(b0), "r"(b1));
}
__device__ __forceinline__ void split2(float v, __nv_bfloat16& h, __nv_bfloat16& l) {
    h = __float2bfloat16(v);
    l = __float2bfloat16(v - __bfloat162float(h));
}

// ---------------- scratch ----------------
#define SZ_R1 (HR_DIM * D_DIM)
#define SZ_E1 (HE_DIM * D_DIM)
#define SZ_F1 (HF_DIM * D_DIM)
#define WOFF_R1 0
#define WOFF_M1 (WOFF_R1 + SZ_R1)
#define WOFF_L1 (WOFF_M1 + SZ_E1)
#define WOFF_M2 (WOFF_L1 + SZ_E1)
#define WOFF_L2 (WOFF_M2 + SZ_E1)
#define WOFF_F1 (WOFF_L2 + SZ_E1)
#define WOFF_F2 (WOFF_F1 + SZ_F1)
#define WPOOL_SZ (WOFF_F2 + SZ_F1)

__device__ __align__(256) __nv_bfloat16 g_whi[WPOOL_SZ];
__device__ __align__(256) __nv_bfloat16 g_wlo[WPOOL_SZ];
__device__ __align__(256) __nv_bfloat16 g_xhi[B_ROWS * D_DIM];
__device__ __align__(256) __nv_bfloat16 g_xlo[B_ROWS * D_DIM];
__device__ __align__(256) float g_H[B_ROWS * HR_DIM];
__device__ __align__(256) __nv_bfloat16 g_xehi[ROWS_PAD * D_DIM];
__device__ __align__(256) __nv_bfloat16 g_xelo[ROWS_PAD * D_DIM];
__device__ __align__(256) __nv_bfloat16 g_y1hi[(size_t)ROWS_PAD * HE_DIM];
__device__ __align__(256) __nv_bfloat16 g_y1lo[(size_t)ROWS_PAD * HE_DIM];
__device__ __align__(256) float g_Ff[B_ROWS * D_DIM];
__device__ __align__(256) __nv_bfloat16 g_fhi[B_ROWS * D_DIM];
__device__ __align__(256) __nv_bfloat16 g_flo[B_ROWS * D_DIM];
__device__ __align__(256) __nv_bfloat16 g_ghi[B_ROWS * HF_DIM];
__device__ __align__(256) __nv_bfloat16 g_glo[B_ROWS * HF_DIM];
__device__ float g_w[B_ROWS];
__device__ int g_hint[B_ROWS];
__device__ int g_list[2 * B_ROWS];
__device__ int g_cnt[2];
__device__ int g_A0;
__device__ int g_cmap[ROWS_PAD];

__global__ void reset_kernel() {
    if (threadIdx.x < 2) g_cnt[threadIdx.x] = 0;
}
__global__ void calca0_kernel() { g_A0 = ((g_cnt[0] + 127) >> 7) << 7; }

// ---------------- merged weight conversion: [K,N] fp32 -> hi/lo bf16 [N,K] ----------
__device__ __forceinline__ void wconv_tile(const float* __restrict__ W,
                                           __nv_bfloat16* __restrict__ hi,
                                           __nv_bfloat16* __restrict__ lo,
                                           int K, int N, int bx, int by) {
    __shared__ float t[32][33];
    int k0 = by * 32, n0 = bx * 32;
    int tx = threadIdx.x, ty = threadIdx.y;
#pragma unroll
    for (int j = 0; j < 4; j++)
        t[ty + j * 8][tx] = W[(size_t)(k0 + ty + j * 8) * N + n0 + tx];
    __syncthreads();
#pragma unroll
    for (int j = 0; j < 4; j++) {
        int n = n0 + ty + j * 8, k = k0 + tx;
        __nv_bfloat16 h, l;
        split2(t[tx][ty + j * 8], h, l);
        hi[(size_t)n * K + k] = h;
        lo[(size_t)n * K + k] = l;
    }
}

// segments: R1(512) M1(4096) L1(4096) M2(4096) L2(4096) F1(2048) F2(2048)
__global__ void wconv_all_kernel(const float* W_r1, const float* W_m1, const float* W_l1,
                                 const float* W_m2, const float* W_l2,
                                 const float* W_f1, const float* W_f2) {
    __nv_bfloat16* hi = g_whi;
    __nv_bfloat16* lo = g_wlo;
    int b = blockIdx.x;
    if (b < 512) {  // R1: K=1024 N=512, gx=16
        wconv_tile(W_r1, hi + WOFF_R1, lo + WOFF_R1, D_DIM, HR_DIM, b % 16, b / 16);
        return;
    }
    b -= 512;
    if (b < 4096) {  // M1: K=1024 N=4096, gx=128
        wconv_tile(W_m1, hi + WOFF_M1, lo + WOFF_M1, D_DIM, HE_DIM, b % 128, b / 128);
        return;
    }
    b -= 4096;
    if (b < 4096) {  // L1
        wconv_tile(W_l1, hi + WOFF_L1, lo + WOFF_L1, D_DIM, HE_DIM, b % 128, b / 128);
        return;
    }
    b -= 4096;
    if (b < 4096) {  // M2: K=4096 N=1024, gx=32
        wconv_tile(W_m2, hi + WOFF_M2, lo + WOFF_M2, HE_DIM, D_DIM, b % 32, b / 32);
        return;
    }
    b -= 4096;
    if (b < 4096) {  // L2
        wconv_tile(W_l2, hi + WOFF_L2, lo + WOFF_L2, HE_DIM, D_DIM, b % 32, b / 32);
        return;
    }
    b -= 4096;
    if (b < 2048) {  // F1: K=1024 N=2048, gx=64
        wconv_tile(W_f1, hi + WOFF_F1, lo + WOFF_F1, D_DIM, HF_DIM, b % 64, b / 64);
        return;
    }
    b -= 2048;
    // F2: K=2048 N=1024, gx=32
    wconv_tile(W_f2, hi + WOFF_F2, lo + WOFF_F2, HF_DIM, D_DIM, b % 32, b / 32);
}
#define WCONV_BLOCKS (512 + 4 * 4096 + 2 * 2048)

__global__ void xconv_kernel(const float* __restrict__ x) {
    size_t i = ((size_t)blockIdx.x * blockDim.x + threadIdx.x) * 4;
    float4 v = *(const float4*)(x + i);
    __nv_bfloat16 h, l;
    split2(v.x, h, l); g_xhi[i] = h;     g_xlo[i] = l;
    split2(v.y, h, l); g_xhi[i + 1] = h; g_xlo[i + 1] = l;
    split2(v.z, h, l); g_xhi[i + 2] = h; g_xlo[i + 2] = l;
    split2(v.w, h, l); g_xhi[i + 3] = h; g_xlo[i + 3] = l;
}

__global__ void router_head_kernel(const float* __restrict__ Wdom, const float* __restrict__ bdom,
                                   const float* __restrict__ Wmop, const float* __restrict__ Wlt) {
    int warp = (blockIdx.x * blockDim.x + threadIdx.x) >> 5;
    int lane = threadIdx.x & 31;
    if (warp >= B_ROWS) return;
    const float* h = g_H + (size_t)warp * HR_DIM;
    float a0 = 0, a1 = 0, m0 = 0, m1 = 0, m2 = 0, m3 = 0, l0 = 0, l1 = 0, l2 = 0, l3 = 0;
    for (int i = lane; i < HR_DIM; i += 32) {
        float hv = h[i];
        a0 += hv * Wdom[i * 2];     a1 += hv * Wdom[i * 2 + 1];
        m0 += hv * Wmop[i * 4];     m1 += hv * Wmop[i * 4 + 1];
        m2 += hv * Wmop[i * 4 + 2]; m3 += hv * Wmop[i * 4 + 3];
        l0 += hv * Wlt[i * 4];      l1 += hv * Wlt[i * 4 + 1];
        l2 += hv * Wlt[i * 4 + 2];  l3 += hv * Wlt[i * 4 + 3];
    }
#pragma unroll
    for (int o = 16; o > 0; o >>= 1) {
        a0 += __shfl_down_sync(~0u, a0, o); a1 += __shfl_down_sync(~0u, a1, o);
        m0 += __shfl_down_sync(~0u, m0, o); m1 += __shfl_down_sync(~0u, m1, o);
        m2 += __shfl_down_sync(~0u, m2, o); m3 += __shfl_down_sync(~0u, m3, o);
        l0 += __shfl_down_sync(~0u, l0, o); l1 += __shfl_down_sync(~0u, l1, o);
        l2 += __shfl_down_sync(~0u, l2, o); l3 += __shfl_down_sync(~0u, l3, o);
    }
    if (lane == 0) {
        a0 += bdom[0]; a1 += bdom[1];
        int primary = (a1 > a0) ? 1 : 0;
        float w = 1.f / (1.f + expf((primary ? a0 : a1) - (primary ? a1 : a0)));
        int mop = 0; float b = m0;
        if (m1 > b) { b = m1; mop = 1; }
        if (m2 > b) { b = m2; mop = 2; }
        if (m3 > b) { b = m3; mop = 3; }
        int lt = 0; b = l0;
        if (l1 > b) { b = l1; lt = 1; }
        if (l2 > b) { b = l2; lt = 2; }
        if (l3 > b) { b = l3; lt = 3; }
        g_w[warp] = w;
        g_hint[warp] = primary ? lt : mop;
        int pos = atomicAdd(&g_cnt[primary], 1);
        g_list[primary * B_ROWS + pos] = warp;
    }
}

__global__ void gather_kernel(const float* __restrict__ x, const float* __restrict__ op_emb,
                              const float* __restrict__ task_emb) {
    int bidx = blockIdx.x;
    int c0 = g_cnt[0], c1 = g_cnt[1], A0 = g_A0;
    int orig = -1;
    const float* er = nullptr;
    if (bidx < c0) {
        orig = g_list[bidx];
        er = op_emb + (size_t)g_hint[orig] * D_DIM;
    } else if (bidx >= A0 && bidx < A0 + c1) {
        orig = g_list[B_ROWS + bidx - A0];
        er = task_emb + (size_t)g_hint[orig] * D_DIM;
    }
    if (threadIdx.x == 0) g_cmap[bidx] = orig;
    if (orig < 0) return;
    const float* xr = x + (size_t)orig * D_DIM;
    size_t ob = (size_t)bidx * D_DIM;
    for (int i = threadIdx.x * 4; i < D_DIM; i += 512) {
        float4 xv = *(const float4*)(xr + i);
        float4 ev = *(const float4*)(er + i);
        float s[4] = {xv.x + ev.x, xv.y + ev.y, xv.z + ev.z, xv.w + ev.w};
#pragma unroll
        for (int j = 0; j < 4; j++) {
            __nv_bfloat16 h, l;
            split2(s[j], h, l);
            g_xehi[ob + i + j] = h;
            g_xelo[ob + i + j] = l;
        }
    }
}

// ---------------- HMMA bf16x3 GEMM: 128x256 tile, BK=32, 4-slot cp.async, 1 sync/iter
// SMEM stage = A(128r x 128B) + B(256r x 128B); row = [hi 64B | lo 64B], XOR swizzle
#define STAGE_BYTES 49152
#define A_BYTES 16384
#define DYN_SMEM (4 * STAGE_BYTES + 128)

template <bool RELU, bool SCAT, bool RESID, bool WF32, bool WBF, bool LOLO>
__global__ void __launch_bounds__(512, 1) mm_hmma(
    const __nv_bfloat16* __restrict__ Ahi, const __nv_bfloat16* __restrict__ Alo,
    const __nv_bfloat16* __restrict__ Bhi, const __nv_bfloat16* __restrict__ Blo,
    const float* __restrict__ bias, float* __restrict__ Cf,
    __nv_bfloat16* __restrict__ Chi, __nv_bfloat16* __restrict__ Clo,
    const float* __restrict__ resid, int N, int K,
    const int* __restrict__ mbase, const int* __restrict__ mcount) {
    if (mcount && (int)blockIdx.y * 128 >= *mcount) return;
    const int m0 = (mbase ? *mbase : 0) + blockIdx.y * 128;
    const int n0 = blockIdx.x * 256;
    const int tid = threadIdx.x;
    const int lane = tid & 31, wid = tid >> 5;
    const int wm = wid & 3, wn = wid >> 2;  // 4x4 warp grid: warp tile 32x64

    extern __shared__ char sm_raw[];
    char* sm = (char*)(((uintptr_t)sm_raw + 127) & ~(uintptr_t)127);
    const uint32_t sbase = smem_u32(sm);

    float acc[2][8][4];
#pragma unroll
    for (int a = 0; a < 2; a++)
#pragma unroll
        for (int b = 0; b < 8; b++)
#pragma unroll
            for (int c = 0; c < 4; c++) acc[a][b][c] = 0.f;

    const int niter = K >> 5;

    auto issue = [&](int it) {
        const int slot = it & 3;
        const int k0 = it << 5;
        const uint32_t as = sbase + slot * STAGE_BYTES;
        const uint32_t bs = as + A_BYTES;
        // A: 128 rows x 8 chunks = 1024 cp16, 512 threads -> 2 reps
#pragma unroll
        for (int rep = 0; rep < 2; rep++) {
            int c = rep * 512 + tid;
            int r = c >> 3, j8 = c & 7;
            uint32_t loc = (uint32_t)(r * 128 + ((j8 * 16) ^ ((r & 7) << 4)));
            const __nv_bfloat16* src =
                ((j8 >> 2) ? Alo : Ahi) + (size_t)(m0 + r) * K + k0 + (j8 & 3) * 8;
            cp16(as + loc, src);
        }
        // B: 256 rows x 8 chunks = 2048 cp16 -> 4 reps
#pragma unroll
        for (int rep = 0; rep < 4; rep++) {
            int c = rep * 512 + tid;
            int r = c >> 3, j8 = c & 7;
            uint32_t loc = (uint32_t)(r * 128 + ((j8 * 16) ^ ((r & 7) << 4)));
            const __nv_bfloat16* src =
                ((j8 >> 2) ? Blo : Bhi) + (size_t)(n0 + r) * K + k0 + (j8 & 3) * 8;
            cp16(bs + loc, src);
        }
    };

    auto compute = [&](int slot) {
        const uint32_t as = sbase + slot * STAGE_BYTES;
        const uint32_t bs = as + A_BYTES;
#pragma unroll
        for (int ks = 0; ks < 2; ks++) {
            const int kb = ks * 32;
            uint32_t ah[2][4], al[2][4];
#pragma unroll
            for (int mt = 0; mt < 2; mt++) {
                int r = wm * 32 + mt * 16 + (lane & 15);
                int sw = (r & 7) << 4;
                uint32_t rb = as + r * 128;
                int bo = kb + ((lane >> 4) << 4);
                ldsm4(ah[mt][0], ah[mt][1], ah[mt][2], ah[mt][3], rb + (uint32_t)(bo ^ sw));
                ldsm4(al[mt][0], al[mt][1], al[mt][2], al[mt][3],
                      rb + (uint32_t)((bo + 64) ^ sw));
            }
#pragma unroll
            for (int np = 0; np < 4; np++) {
                int r = wn * 64 + np * 16 + (lane & 7) + ((lane >> 4) << 3);
                int sw = (r & 7) << 4;
                uint32_t rb = bs + r * 128;
                int bo = kb + (((lane >> 3) & 1) << 4);
                uint32_t bh[4], bl[4];
                ldsm4(bh[0], bh[1], bh[2], bh[3], rb + (uint32_t)(bo ^ sw));
                ldsm4(bl[0], bl[1], bl[2], bl[3], rb + (uint32_t)((bo + 64) ^ sw));
#pragma unroll
                for (int mt = 0; mt < 2; mt++) {
                    mma16816(acc[mt][np * 2],     ah[mt], bh[0], bh[1]);
                    mma16816(acc[mt][np * 2 + 1], ah[mt], bh[2], bh[3]);
                    mma16816(acc[mt][np * 2],     ah[mt], bl[0], bl[1]);
                    mma16816(acc[mt][np * 2 + 1], ah[mt], bl[2], bl[3]);
                    mma16816(acc[mt][np * 2],     al[mt], bh[0], bh[1]);
                    mma16816(acc[mt][np * 2 + 1], al[mt], bh[2], bh[3]);
                    if (LOLO) {
                        mma16816(acc[mt][np * 2],     al[mt], bl[0], bl[1]);
                        mma16816(acc[mt][np * 2 + 1], al[mt], bl[2], bl[3]);
                    }
                }
            }
        }
    };

    // prologue: 3 groups in flight over 4 slots
    issue(0); CP_COMMIT;
    issue(1); CP_COMMIT;
    issue(2); CP_COMMIT;
    for (int i = 0; i < niter; i++) {
        CP_WAIT2;          // group i complete
        __syncthreads();   // everyone done with compute(i-1) (slot (i-1)&3)
        if (i + 3 < niter) issue(i + 3);  // writes slot (i+3)&3 == (i-1)&3 — safe
        CP_COMMIT;
        compute(i & 3);
    }

    // ---- epilogue ----
    const int tg = lane & 3, g = lane >> 2;
#pragma unroll
    for (int mt = 0; mt < 2; mt++) {
#pragma unroll
        for (int h2 = 0; h2 < 2; h2++) {
            int row = m0 + wm * 32 + mt * 16 + g + h2 * 8;
            int orig = row;
            float wsc = 1.f;
            bool valid = true;
            if (SCAT) {
                orig = g_cmap[row];
                valid = orig >= 0;
                wsc = valid ? g_w[orig] : 0.f;
            }
            if (!valid) continue;
            size_t rowoff = (size_t)orig * N;
#pragma unroll
            for (int nt = 0; nt < 8; nt++) {
                int col = n0 + wn * 64 + nt * 8 + tg * 2;
                float v0 = acc[mt][nt][h2 * 2]     + bias[col];
                float v1 = acc[mt][nt][h2 * 2 + 1] + bias[col + 1];
                if (RELU) { v0 = fmaxf(v0, 0.f); v1 = fmaxf(v1, 0.f); }
                if (SCAT) { v0 *= wsc; v1 *= wsc; }
                if (RESID) {
                    float2 rv = *(const float2*)(resid + rowoff + col);
                    v0 += rv.x; v1 += rv.y;
                }
                if (WF32) {
                    float2 o; o.x = v0; o.y = v1;
                    *(float2*)(Cf + rowoff + col) = o;
                }
                if (WBF) {
                    __nv_bfloat16 h0, l0, h1, l1;
                    split2(v0, h0, l0);
                    split2(v1, h1, l1);
                    __nv_bfloat162 hh; hh.x = h0; hh.y = h1;
                    __nv_bfloat162 ll; ll.x = l0; ll.y = l1;
                    *(__nv_bfloat162*)(Chi + rowoff + col) = hh;
                    *(__nv_bfloat162*)(Clo + rowoff + col) = ll;
                }
            }
        }
    }
}

// ---------------- launch ----------------
extern "C" void kernel_launch(void* const* d_in, const int* in_sizes, int n_in,
                              void* d_out, int out_size) {
    const float* x        = (const float*)d_in[0];
    const float* W_r1     = (const float*)d_in[1];
    const float* b_r1     = (const float*)d_in[2];
    const float* W_dom    = (const float*)d_in[3];
    const float* b_dom    = (const float*)d_in[4];
    const float* W_mop    = (const float*)d_in[5];
    const float* W_lt     = (const float*)d_in[6];
    const float* op_emb   = (const float*)d_in[7];
    const float* W_m1     = (const float*)d_in[8];
    const float* b_m1     = (const float*)d_in[9];
    const float* W_m2     = (const float*)d_in[10];
    const float* b_m2     = (const float*)d_in[11];
    const float* task_emb = (const float*)d_in[12];
    const float* W_l1     = (const float*)d_in[13];
    const float* b_l1     = (const float*)d_in[14];
    const float* W_l2     = (const float*)d_in[15];
    const float* b_l2     = (const float*)d_in[16];
    const float* W_f1     = (const float*)d_in[17];
    const float* b_f1     = (const float*)d_in[18];
    const float* W_f2     = (const float*)d_in[19];
    const float* b_f2     = (const float*)d_in[20];
    float* out = (float*)d_out;

    __nv_bfloat16 *whi, *wlo, *xhi, *xlo, *xehi, *xelo, *y1hi, *y1lo, *fhi, *flo, *ghi, *glo;
    float *H, *Ff;
    int *cnt, *A0;
    cudaGetSymbolAddress((void**)&whi, g_whi);
    cudaGetSymbolAddress((void**)&wlo, g_wlo);
    cudaGetSymbolAddress((void**)&xhi, g_xhi);
    cudaGetSymbolAddress((void**)&xlo, g_xlo);
    cudaGetSymbolAddress((void**)&xehi, g_xehi);
    cudaGetSymbolAddress((void**)&xelo, g_xelo);
    cudaGetSymbolAddress((void**)&y1hi, g_y1hi);
    cudaGetSymbolAddress((void**)&y1lo, g_y1lo);
    cudaGetSymbolAddress((void**)&fhi, g_fhi);
    cudaGetSymbolAddress((void**)&flo, g_flo);
    cudaGetSymbolAddress((void**)&ghi, g_ghi);
    cudaGetSymbolAddress((void**)&glo, g_glo);
    cudaGetSymbolAddress((void**)&H, g_H);
    cudaGetSymbolAddress((void**)&Ff, g_Ff);
    cudaGetSymbolAddress((void**)&cnt, g_cnt);
    cudaGetSymbolAddress((void**)&A0, g_A0);

    cudaFuncSetAttribute((const void*)mm_hmma<true, false, false, true, false, true>,
                         cudaFuncAttributeMaxDynamicSharedMemorySize, DYN_SMEM);
    cudaFuncSetAttribute((const void*)mm_hmma<true, false, false, false, true, false>,
                         cudaFuncAttributeMaxDynamicSharedMemorySize, DYN_SMEM);
    cudaFuncSetAttribute((const void*)mm_hmma<false, true, false, true, true, false>,
                         cudaFuncAttributeMaxDynamicSharedMemorySize, DYN_SMEM);
    cudaFuncSetAttribute((const void*)mm_hmma<false, false, true, true, false, false>,
                         cudaFuncAttributeMaxDynamicSharedMemorySize, DYN_SMEM);

    dim3 blk(512);
    int mtiles = B_ROWS / 128;

    reset_kernel<<<1, 32>>>();
    wconv_all_kernel<<<WCONV_BLOCKS, dim3(32, 8)>>>(W_r1, W_m1, W_l1, W_m2, W_l2, W_f1, W_f2);
    xconv_kernel<<<B_ROWS * D_DIM / 1024, 256>>>(x);

    // router: H = relu(x @ W_r1 + b_r1)  (bf16x4)
    mm_hmma<true, false, false, true, false, true><<<dim3(HR_DIM / 256, mtiles), blk, DYN_SMEM>>>(
        xhi, xlo, whi + WOFF_R1, wlo + WOFF_R1, b_r1, H, nullptr, nullptr, nullptr,
        HR_DIM, D_DIM, nullptr, nullptr);
    router_head_kernel<<<B_ROWS / 8, 256>>>(W_dom, b_dom, W_mop, W_lt);
    calca0_kernel<<<1, 1>>>();
    gather_kernel<<<ROWS_PAD, 128>>>(x, op_emb, task_emb);

    // expert layer 1 (compact dense): Y1 = relu(XE @ W1 + b1)
    mm_hmma<true, false, false, false, true, false><<<dim3(HE_DIM / 256, mtiles), blk, DYN_SMEM>>>(
        xehi, xelo, whi + WOFF_M1, wlo + WOFF_M1, b_m1, nullptr, y1hi, y1lo, nullptr,
        HE_DIM, D_DIM, nullptr, cnt);
    mm_hmma<true, false, false, false, true, false><<<dim3(HE_DIM / 256, mtiles), blk, DYN_SMEM>>>(
        xehi, xelo, whi + WOFF_L1, wlo + WOFF_L1, b_l1, nullptr, y1hi, y1lo, nullptr,
        HE_DIM, D_DIM, A0, cnt + 1);
    // expert layer 2: FUSED[orig] = w * (Y1 @ W2 + b2), scatter
    mm_hmma<false, true, false, true, true, false><<<dim3(D_DIM / 256, mtiles), blk, DYN_SMEM>>>(
        y1hi, y1lo, whi + WOFF_M2, wlo + WOFF_M2, b_m2, Ff, fhi, flo, nullptr,
        D_DIM, HE_DIM, nullptr, cnt);
    mm_hmma<false, true, false, true, true, false><<<dim3(D_DIM / 256, mtiles), blk, DYN_SMEM>>>(
        y1hi, y1lo, whi + WOFF_L2, wlo + WOFF_L2, b_l2, Ff, fhi, flo, nullptr,
        D_DIM, HE_DIM, A0, cnt + 1);
    // fusion layer 1: G = relu(FUSED @ W_f1 + b_f1)
    mm_hmma<true, false, false, false, true, false><<<dim3(HF_DIM / 256, mtiles), blk, DYN_SMEM>>>(
        fhi, flo, whi + WOFF_F1, wlo + WOFF_F1, b_f1, nullptr, ghi, glo, nullptr,
        HF_DIM, D_DIM, nullptr, nullptr);
    // fusion layer 2: out = FUSED + G @ W_f2 + b_f2
    mm_hmma<false, false, true, true, false, false><<<dim3(D_DIM / 256, mtiles), blk, DYN_SMEM>>>(
        ghi, glo, whi + WOFF_F2, wlo + WOFF_F2, b_f2, out, nullptr, nullptr, Ff,
        D_DIM, HF_DIM, nullptr, nullptr);
}

// round 8
// speedup vs baseline: 3.2775x; 1.1287x over previous
#include <cuda_runtime.h>
#include <cuda_bf16.h>
#include <stdint.h>
#include <math.h>

#define B_ROWS 8192
#define ROWS_PAD 8448
#define D_DIM 1024
#define HR_DIM 512
#define HE_DIM 4096
#define HF_DIM 2048

// ---------------- PTX helpers (base sm_103-safe) ----------------
__device__ __forceinline__ uint32_t smem_u32(const void* p) {
    uint32_t a;
    asm("{ .reg .u64 t; cvta.to.shared.u64 t, %1; cvt.u32.u64 %0, t; }" : "=r"(a) : "l"(p));
    return a;
}
__device__ __forceinline__ void cp16(uint32_t dst, const void* src) {
    asm volatile("cp.async.cg.shared.global [%0], [%1], 16;" :: "r"(dst), "l"(src));
}
#define CP_COMMIT asm volatile("cp.async.commit_group;" ::: "memory")
#define CP_WAIT2  asm volatile("cp.async.wait_group 2;" ::: "memory")

__device__ __forceinline__ void ldsm4(uint32_t& r0, uint32_t& r1, uint32_t& r2, uint32_t& r3,
                                      uint32_t a) {
    asm volatile("ldmatrix.sync.aligned.m8n8.x4.shared.b16 {%0,%1,%2,%3}, [%4];"
                 : "=r"(r0), "=r"(r1), "=r"(r2), "=r"(r3) : "r"(a));
}
__device__ __forceinline__ void mma16816(float (&d)[4], const uint32_t (&a)[4],
                                         uint32_t b0, uint32_t b1) {
    asm volatile(
        "mma.sync.aligned.m16n8k16.row.col.f32.bf16.bf16.f32 "
        "{%0,%1,%2,%3}, {%4,%5,%6,%7}, {%8,%9}, {%0,%1,%2,%3};"
        : "+f"(d[0]), "+f"(d[1]), "+f"(d[2]), "+f"(d[3])
        : "r"(a[0]), "r"(a[1]), "r"(a[2]), "r"(a[3]), "r"(b0), "r"(b1));
}
__device__ __forceinline__ void split2(float v, __nv_bfloat16& h, __nv_bfloat16& l) {
    h = __float2bfloat16(v);
    l = __float2bfloat16(v - __bfloat162float(h));
}

// ---------------- scratch ----------------
#define SZ_R1 (HR_DIM * D_DIM)
#define SZ_E1 (HE_DIM * D_DIM)
#define SZ_F1 (HF_DIM * D_DIM)
#define WOFF_R1 0
#define WOFF_M1 (WOFF_R1 + SZ_R1)
#define WOFF_L1 (WOFF_M1 + SZ_E1)
#define WOFF_M2 (WOFF_L1 + SZ_E1)
#define WOFF_L2 (WOFF_M2 + SZ_E1)
#define WOFF_F1 (WOFF_L2 + SZ_E1)
#define WOFF_F2 (WOFF_F1 + SZ_F1)
#define WPOOL_SZ (WOFF_F2 + SZ_F1)

__device__ __align__(256) __nv_bfloat16 g_whi[WPOOL_SZ];
__device__ __align__(256) __nv_bfloat16 g_wlo[WPOOL_SZ];
__device__ __align__(256) __nv_bfloat16 g_xhi[B_ROWS * D_DIM];
__device__ __align__(256) __nv_bfloat16 g_xlo[B_ROWS * D_DIM];
__device__ __align__(256) float g_H[B_ROWS * HR_DIM];
__device__ __align__(256) __nv_bfloat16 g_xehi[ROWS_PAD * D_DIM];
__device__ __align__(256) __nv_bfloat16 g_xelo[ROWS_PAD * D_DIM];
__device__ __align__(256) __nv_bfloat16 g_y1hi[(size_t)ROWS_PAD * HE_DIM];
__device__ __align__(256) __nv_bfloat16 g_y1lo[(size_t)ROWS_PAD * HE_DIM];
__device__ __align__(256) float g_Ff[B_ROWS * D_DIM];
__device__ __align__(256) __nv_bfloat16 g_fhi[B_ROWS * D_DIM];
__device__ __align__(256) __nv_bfloat16 g_flo[B_ROWS * D_DIM];
__device__ __align__(256) __nv_bfloat16 g_ghi[B_ROWS * HF_DIM];
__device__ __align__(256) __nv_bfloat16 g_glo[B_ROWS * HF_DIM];
__device__ float g_w[B_ROWS];
__device__ int g_hint[B_ROWS];
__device__ int g_list[2 * B_ROWS];
__device__ int g_cnt[2];
__device__ int g_A0;
__device__ int g_cmap[ROWS_PAD];

__global__ void reset_kernel() {
    if (threadIdx.x < 2) g_cnt[threadIdx.x] = 0;
}
__global__ void calca0_kernel() { g_A0 = ((g_cnt[0] + 127) >> 7) << 7; }

// ---------------- merged weight conversion: [K,N] fp32 -> hi/lo bf16 [N,K] ----------
__device__ __forceinline__ void wconv_tile(const float* __restrict__ W,
                                           __nv_bfloat16* __restrict__ hi,
                                           __nv_bfloat16* __restrict__ lo,
                                           int K, int N, int bx, int by) {
    __shared__ float t[32][33];
    int k0 = by * 32, n0 = bx * 32;
    int tx = threadIdx.x, ty = threadIdx.y;
#pragma unroll
    for (int j = 0; j < 4; j++)
        t[ty + j * 8][tx] = W[(size_t)(k0 + ty + j * 8) * N + n0 + tx];
    __syncthreads();
#pragma unroll
    for (int j = 0; j < 4; j++) {
        int n = n0 + ty + j * 8, k = k0 + tx;
        __nv_bfloat16 h, l;
        split2(t[tx][ty + j * 8], h, l);
        hi[(size_t)n * K + k] = h;
        lo[(size_t)n * K + k] = l;
    }
}

__global__ void wconv_all_kernel(const float* W_r1, const float* W_m1, const float* W_l1,
                                 const float* W_m2, const float* W_l2,
                                 const float* W_f1, const float* W_f2) {
    __nv_bfloat16* hi = g_whi;
    __nv_bfloat16* lo = g_wlo;
    int b = blockIdx.x;
    if (b < 512) { wconv_tile(W_r1, hi + WOFF_R1, lo + WOFF_R1, D_DIM, HR_DIM, b % 16, b / 16); return; }
    b -= 512;
    if (b < 4096) { wconv_tile(W_m1, hi + WOFF_M1, lo + WOFF_M1, D_DIM, HE_DIM, b % 128, b / 128); return; }
    b -= 4096;
    if (b < 4096) { wconv_tile(W_l1, hi + WOFF_L1, lo + WOFF_L1, D_DIM, HE_DIM, b % 128, b / 128); return; }
    b -= 4096;
    if (b < 4096) { wconv_tile(W_m2, hi + WOFF_M2, lo + WOFF_M2, HE_DIM, D_DIM, b % 32, b / 32); return; }
    b -= 4096;
    if (b < 4096) { wconv_tile(W_l2, hi + WOFF_L2, lo + WOFF_L2, HE_DIM, D_DIM, b % 32, b / 32); return; }
    b -= 4096;
    if (b < 2048) { wconv_tile(W_f1, hi + WOFF_F1, lo + WOFF_F1, D_DIM, HF_DIM, b % 64, b / 64); return; }
    b -= 2048;
    wconv_tile(W_f2, hi + WOFF_F2, lo + WOFF_F2, HF_DIM, D_DIM, b % 32, b / 32);
}
#define WCONV_BLOCKS (512 + 4 * 4096 + 2 * 2048)

__global__ void xconv_kernel(const float* __restrict__ x) {
    size_t i = ((size_t)blockIdx.x * blockDim.x + threadIdx.x) * 4;
    float4 v = *(const float4*)(x + i);
    __nv_bfloat16 h, l;
    split2(v.x, h, l); g_xhi[i] = h;     g_xlo[i] = l;
    split2(v.y, h, l); g_xhi[i + 1] = h; g_xlo[i + 1] = l;
    split2(v.z, h, l); g_xhi[i + 2] = h; g_xlo[i + 2] = l;
    split2(v.w, h, l); g_xhi[i + 3] = h; g_xlo[i + 3] = l;
}

__global__ void router_head_kernel(const float* __restrict__ Wdom, const float* __restrict__ bdom,
                                   const float* __restrict__ Wmop, const float* __restrict__ Wlt) {
    int warp = (blockIdx.x * blockDim.x + threadIdx.x) >> 5;
    int lane = threadIdx.x & 31;
    if (warp >= B_ROWS) return;
    const float* h = g_H + (size_t)warp * HR_DIM;
    float a0 = 0, a1 = 0, m0 = 0, m1 = 0, m2 = 0, m3 = 0, l0 = 0, l1 = 0, l2 = 0, l3 = 0;
    for (int i = lane; i < HR_DIM; i += 32) {
        float hv = h[i];
        a0 += hv * Wdom[i * 2];     a1 += hv * Wdom[i * 2 + 1];
        m0 += hv * Wmop[i * 4];     m1 += hv * Wmop[i * 4 + 1];
        m2 += hv * Wmop[i * 4 + 2]; m3 += hv * Wmop[i * 4 + 3];
        l0 += hv * Wlt[i * 4];      l1 += hv * Wlt[i * 4 + 1];
        l2 += hv * Wlt[i * 4 + 2];  l3 += hv * Wlt[i * 4 + 3];
    }
#pragma unroll
    for (int o = 16; o > 0; o >>= 1) {
        a0 += __shfl_down_sync(~0u, a0, o); a1 += __shfl_down_sync(~0u, a1, o);
        m0 += __shfl_down_sync(~0u, m0, o); m1 += __shfl_down_sync(~0u, m1, o);
        m2 += __shfl_down_sync(~0u, m2, o); m3 += __shfl_down_sync(~0u, m3, o);
        l0 += __shfl_down_sync(~0u, l0, o); l1 += __shfl_down_sync(~0u, l1, o);
        l2 += __shfl_down_sync(~0u, l2, o); l3 += __shfl_down_sync(~0u, l3, o);
    }
    if (lane == 0) {
        a0 += bdom[0]; a1 += bdom[1];
        int primary = (a1 > a0) ? 1 : 0;
        float w = 1.f / (1.f + expf((primary ? a0 : a1) - (primary ? a1 : a0)));
        int mop = 0; float b = m0;
        if (m1 > b) { b = m1; mop = 1; }
        if (m2 > b) { b = m2; mop = 2; }
        if (m3 > b) { b = m3; mop = 3; }
        int lt = 0; b = l0;
        if (l1 > b) { b = l1; lt = 1; }
        if (l2 > b) { b = l2; lt = 2; }
        if (l3 > b) { b = l3; lt = 3; }
        g_w[warp] = w;
        g_hint[warp] = primary ? lt : mop;
        int pos = atomicAdd(&g_cnt[primary], 1);
        g_list[primary * B_ROWS + pos] = warp;
    }
}

__global__ void gather_kernel(const float* __restrict__ x, const float* __restrict__ op_emb,
                              const float* __restrict__ task_emb) {
    int bidx = blockIdx.x;
    int c0 = g_cnt[0], c1 = g_cnt[1], A0 = g_A0;
    int orig = -1;
    const float* er = nullptr;
    if (bidx < c0) {
        orig = g_list[bidx];
        er = op_emb + (size_t)g_hint[orig] * D_DIM;
    } else if (bidx >= A0 && bidx < A0 + c1) {
        orig = g_list[B_ROWS + bidx - A0];
        er = task_emb + (size_t)g_hint[orig] * D_DIM;
    }
    if (threadIdx.x == 0) g_cmap[bidx] = orig;
    if (orig < 0) return;
    const float* xr = x + (size_t)orig * D_DIM;
    size_t ob = (size_t)bidx * D_DIM;
    for (int i = threadIdx.x * 4; i < D_DIM; i += 512) {
        float4 xv = *(const float4*)(xr + i);
        float4 ev = *(const float4*)(er + i);
        float s[4] = {xv.x + ev.x, xv.y + ev.y, xv.z + ev.z, xv.w + ev.w};
#pragma unroll
        for (int j = 0; j < 4; j++) {
            __nv_bfloat16 h, l;
            split2(s[j], h, l);
            g_xehi[ob + i + j] = h;
            g_xelo[ob + i + j] = l;
        }
    }
}

// ---------------- HMMA bf16x3 GEMM: 128x256 tile, BK=32, 4-slot cp.async ----------
// Pass-major MMA order: same-acc reuse distance = 16 MMAs (breaks RAW chains).
// MERGE: per-m-tile weight/bias select between two experts via g_A0; limit=g_A0+g_cnt[1].
#define STAGE_BYTES 49152
#define A_BYTES 16384
#define DYN_SMEM (4 * STAGE_BYTES + 128)

template <bool RELU, bool SCAT, bool RESID, bool WF32, bool WBF, bool LOLO, bool MERGE>
__global__ void __launch_bounds__(512, 1) mm_hmma(
    const __nv_bfloat16* __restrict__ Ahi, const __nv_bfloat16* __restrict__ Alo,
    const __nv_bfloat16* __restrict__ Bhi, const __nv_bfloat16* __restrict__ Blo,
    const __nv_bfloat16* __restrict__ B2hi, const __nv_bfloat16* __restrict__ B2lo,
    const float* __restrict__ bias, const float* __restrict__ bias2,
    float* __restrict__ Cf, __nv_bfloat16* __restrict__ Chi, __nv_bfloat16* __restrict__ Clo,
    const float* __restrict__ resid, int N, int K) {
    const int m0 = blockIdx.y * 128;
    if (MERGE) {
        if (m0 >= g_A0 + g_cnt[1]) return;
        if (m0 >= g_A0) { Bhi = B2hi; Blo = B2lo; bias = bias2; }
    }
    const int n0 = blockIdx.x * 256;
    const int tid = threadIdx.x;
    const int lane = tid & 31, wid = tid >> 5;
    const int wm = wid & 3, wn = wid >> 2;  // 4x4 warp grid: warp tile 32x64

    extern __shared__ char sm_raw[];
    char* sm = (char*)(((uintptr_t)sm_raw + 127) & ~(uintptr_t)127);
    const uint32_t sbase = smem_u32(sm);

    float acc[2][8][4];
#pragma unroll
    for (int a = 0; a < 2; a++)
#pragma unroll
        for (int b = 0; b < 8; b++)
#pragma unroll
            for (int c = 0; c < 4; c++) acc[a][b][c] = 0.f;

    const int niter = K >> 5;

    auto issue = [&](int it) {
        const int slot = it & 3;
        const int k0 = it << 5;
        const uint32_t as = sbase + slot * STAGE_BYTES;
        const uint32_t bs = as + A_BYTES;
#pragma unroll
        for (int rep = 0; rep < 2; rep++) {
            int c = rep * 512 + tid;
            int r = c >> 3, j8 = c & 7;
            uint32_t loc = (uint32_t)(r * 128 + ((j8 * 16) ^ ((r & 7) << 4)));
            const __nv_bfloat16* src =
                ((j8 >> 2) ? Alo : Ahi) + (size_t)(m0 + r) * K + k0 + (j8 & 3) * 8;
            cp16(as + loc, src);
        }
#pragma unroll
        for (int rep = 0; rep < 4; rep++) {
            int c = rep * 512 + tid;
            int r = c >> 3, j8 = c & 7;
            uint32_t loc = (uint32_t)(r * 128 + ((j8 * 16) ^ ((r & 7) << 4)));
            const __nv_bfloat16* src =
                ((j8 >> 2) ? Blo : Bhi) + (size_t)(n0 + r) * K + k0 + (j8 & 3) * 8;
            cp16(bs + loc, src);
        }
    };

    auto compute = [&](int slot) {
        const uint32_t as = sbase + slot * STAGE_BYTES;
        const uint32_t bs = as + A_BYTES;
#pragma unroll
        for (int ks = 0; ks < 2; ks++) {
            const int kb = ks * 32;
            uint32_t ah[2][4], al[2][4], bq[4][4];
            // A hi+lo (4 ldsm4)
#pragma unroll
            for (int mt = 0; mt < 2; mt++) {
                int r = wm * 32 + mt * 16 + (lane & 15);
                int sw = (r & 7) << 4;
                uint32_t rb = as + r * 128;
                int bo = kb + ((lane >> 4) << 4);
                ldsm4(ah[mt][0], ah[mt][1], ah[mt][2], ah[mt][3], rb + (uint32_t)(bo ^ sw));
                ldsm4(al[mt][0], al[mt][1], al[mt][2], al[mt][3],
                      rb + (uint32_t)((bo + 64) ^ sw));
            }
            // B hi, all np (4 ldsm4)
#pragma unroll
            for (int np = 0; np < 4; np++) {
                int r = wn * 64 + np * 16 + (lane & 7) + ((lane >> 4) << 3);
                int sw = (r & 7) << 4;
                int bo = kb + (((lane >> 3) & 1) << 4);
                ldsm4(bq[np][0], bq[np][1], bq[np][2], bq[np][3],
                      bs + r * 128 + (uint32_t)(bo ^ sw));
            }
            // pass: ah x bh (16 MMAs, all-distinct accs)
#pragma unroll
            for (int np = 0; np < 4; np++)
#pragma unroll
                for (int mt = 0; mt < 2; mt++) {
                    mma16816(acc[mt][np * 2],     ah[mt], bq[np][0], bq[np][1]);
                    mma16816(acc[mt][np * 2 + 1], ah[mt], bq[np][2], bq[np][3]);
                }
            // pass: al x bh
#pragma unroll
            for (int np = 0; np < 4; np++)
#pragma unroll
                for (int mt = 0; mt < 2; mt++) {
                    mma16816(acc[mt][np * 2],     al[mt], bq[np][0], bq[np][1]);
                    mma16816(acc[mt][np * 2 + 1], al[mt], bq[np][2], bq[np][3]);
                }
            // B lo, all np (overwrites bq)
#pragma unroll
            for (int np = 0; np < 4; np++) {
                int r = wn * 64 + np * 16 + (lane & 7) + ((lane >> 4) << 3);
                int sw = (r & 7) << 4;
                int bo = kb + (((lane >> 3) & 1) << 4);
                ldsm4(bq[np][0], bq[np][1], bq[np][2], bq[np][3],
                      bs + r * 128 + (uint32_t)((bo + 64) ^ sw));
            }
            // pass: ah x bl
#pragma unroll
            for (int np = 0; np < 4; np++)
#pragma unroll
                for (int mt = 0; mt < 2; mt++) {
                    mma16816(acc[mt][np * 2],     ah[mt], bq[np][0], bq[np][1]);
                    mma16816(acc[mt][np * 2 + 1], ah[mt], bq[np][2], bq[np][3]);
                }
            if (LOLO) {
#pragma unroll
                for (int np = 0; np < 4; np++)
#pragma unroll
                    for (int mt = 0; mt < 2; mt++) {
                        mma16816(acc[mt][np * 2],     al[mt], bq[np][0], bq[np][1]);
                        mma16816(acc[mt][np * 2 + 1], al[mt], bq[np][2], bq[np][3]);
                    }
            }
        }
    };

    issue(0); CP_COMMIT;
    issue(1); CP_COMMIT;
    issue(2); CP_COMMIT;
    for (int i = 0; i < niter; i++) {
        CP_WAIT2;
        __syncthreads();
        if (i + 3 < niter) issue(i + 3);
        CP_COMMIT;
        compute(i & 3);
    }

    // ---- epilogue ----
    const int tg = lane & 3, g = lane >> 2;
#pragma unroll
    for (int mt = 0; mt < 2; mt++) {
#pragma unroll
        for (int h2 = 0; h2 < 2; h2++) {
            int row = m0 + wm * 32 + mt * 16 + g + h2 * 8;
            int orig = row;
            float wsc = 1.f;
            bool valid = true;
            if (SCAT) {
                orig = g_cmap[row];
                valid = orig >= 0;
                wsc = valid ? g_w[orig] : 0.f;
            }
            if (!valid) continue;
            size_t rowoff = (size_t)orig * N;
#pragma unroll
            for (int nt = 0; nt < 8; nt++) {
                int col = n0 + wn * 64 + nt * 8 + tg * 2;
                float v0 = acc[mt][nt][h2 * 2]     + bias[col];
                float v1 = acc[mt][nt][h2 * 2 + 1] + bias[col + 1];
                if (RELU) { v0 = fmaxf(v0, 0.f); v1 = fmaxf(v1, 0.f); }
                if (SCAT) { v0 *= wsc; v1 *= wsc; }
                if (RESID) {
                    float2 rv = *(const float2*)(resid + rowoff + col);
                    v0 += rv.x; v1 += rv.y;
                }
                if (WF32) {
                    float2 o; o.x = v0; o.y = v1;
                    *(float2*)(Cf + rowoff + col) = o;
                }
                if (WBF) {
                    __nv_bfloat16 h0, l0, h1, l1;
                    split2(v0, h0, l0);
                    split2(v1, h1, l1);
                    __nv_bfloat162 hh; hh.x = h0; hh.y = h1;
                    __nv_bfloat162 ll; ll.x = l0; ll.y = l1;
                    *(__nv_bfloat162*)(Chi + rowoff + col) = hh;
                    *(__nv_bfloat162*)(Clo + rowoff + col) = ll;
                }
            }
        }
    }
}

// ---------------- launch ----------------
extern "C" void kernel_launch(void* const* d_in, const int* in_sizes, int n_in,
                              void* d_out, int out_size) {
    const float* x        = (const float*)d_in[0];
    const float* W_r1     = (const float*)d_in[1];
    const float* b_r1     = (const float*)d_in[2];
    const float* W_dom    = (const float*)d_in[3];
    const float* b_dom    = (const float*)d_in[4];
    const float* W_mop    = (const float*)d_in[5];
    const float* W_lt     = (const float*)d_in[6];
    const float* op_emb   = (const float*)d_in[7];
    const float* W_m1     = (const float*)d_in[8];
    const float* b_m1     = (const float*)d_in[9];
    const float* W_m2     = (const float*)d_in[10];
    const float* b_m2     = (const float*)d_in[11];
    const float* task_emb = (const float*)d_in[12];
    const float* W_l1     = (const float*)d_in[13];
    const float* b_l1     = (const float*)d_in[14];
    const float* W_l2     = (const float*)d_in[15];
    const float* b_l2     = (const float*)d_in[16];
    const float* W_f1     = (const float*)d_in[17];
    const float* b_f1     = (const float*)d_in[18];
    const float* W_f2     = (const float*)d_in[19];
    const float* b_f2     = (const float*)d_in[20];
    float* out = (float*)d_out;

    __nv_bfloat16 *whi, *wlo, *xhi, *xlo, *xehi, *xelo, *y1hi, *y1lo, *fhi, *flo, *ghi, *glo;
    float *H, *Ff;
    cudaGetSymbolAddress((void**)&whi, g_whi);
    cudaGetSymbolAddress((void**)&wlo, g_wlo);
    cudaGetSymbolAddress((void**)&xhi, g_xhi);
    cudaGetSymbolAddress((void**)&xlo, g_xlo);
    cudaGetSymbolAddress((void**)&xehi, g_xehi);
    cudaGetSymbolAddress((void**)&xelo, g_xelo);
    cudaGetSymbolAddress((void**)&y1hi, g_y1hi);
    cudaGetSymbolAddress((void**)&y1lo, g_y1lo);
    cudaGetSymbolAddress((void**)&fhi, g_fhi);
    cudaGetSymbolAddress((void**)&flo, g_flo);
    cudaGetSymbolAddress((void**)&ghi, g_ghi);
    cudaGetSymbolAddress((void**)&glo, g_glo);
    cudaGetSymbolAddress((void**)&H, g_H);
    cudaGetSymbolAddress((void**)&Ff, g_Ff);

    cudaFuncSetAttribute((const void*)mm_hmma<true, false, false, true, false, true, false>,
                         cudaFuncAttributeMaxDynamicSharedMemorySize, DYN_SMEM);
    cudaFuncSetAttribute((const void*)mm_hmma<true, false, false, false, true, false, true>,
                         cudaFuncAttributeMaxDynamicSharedMemorySize, DYN_SMEM);
    cudaFuncSetAttribute((const void*)mm_hmma<false, true, false, true, true, false, true>,
                         cudaFuncAttributeMaxDynamicSharedMemorySize, DYN_SMEM);
    cudaFuncSetAttribute((const void*)mm_hmma<true, false, false, false, true, false, false>,
                         cudaFuncAttributeMaxDynamicSharedMemorySize, DYN_SMEM);
    cudaFuncSetAttribute((const void*)mm_hmma<false, false, true, true, false, false, false>,
                         cudaFuncAttributeMaxDynamicSharedMemorySize, DYN_SMEM);

    dim3 blk(512);
    int mtiles = B_ROWS / 128;
    int mtiles_pad = ROWS_PAD / 128;

    reset_kernel<<<1, 32>>>();
    wconv_all_kernel<<<WCONV_BLOCKS, dim3(32, 8)>>>(W_r1, W_m1, W_l1, W_m2, W_l2, W_f1, W_f2);
    xconv_kernel<<<B_ROWS * D_DIM / 1024, 256>>>(x);

    // router: H = relu(x @ W_r1 + b_r1)  (bf16x4 — argmax-safe)
    mm_hmma<true, false, false, true, false, true, false>
        <<<dim3(HR_DIM / 256, mtiles), blk, DYN_SMEM>>>(
        xhi, xlo, whi + WOFF_R1, wlo + WOFF_R1, nullptr, nullptr, b_r1, nullptr,
        H, nullptr, nullptr, nullptr, HR_DIM, D_DIM);
    router_head_kernel<<<B_ROWS / 8, 256>>>(W_dom, b_dom, W_mop, W_lt);
    calca0_kernel<<<1, 1>>>();
    gather_kernel<<<ROWS_PAD, 128>>>(x, op_emb, task_emb);

    // expert layer 1 (merged math+lang): Y1 = relu(XE @ W1 + b1)
    mm_hmma<true, false, false, false, true, false, true>
        <<<dim3(HE_DIM / 256, mtiles_pad), blk, DYN_SMEM>>>(
        xehi, xelo, whi + WOFF_M1, wlo + WOFF_M1, whi + WOFF_L1, wlo + WOFF_L1, b_m1, b_l1,
        nullptr, y1hi, y1lo, nullptr, HE_DIM, D_DIM);
    // expert layer 2 (merged): FUSED[orig] = w * (Y1 @ W2 + b2), scatter
    mm_hmma<false, true, false, true, true, false, true>
        <<<dim3(D_DIM / 256, mtiles_pad), blk, DYN_SMEM>>>(
        y1hi, y1lo, whi + WOFF_M2, wlo + WOFF_M2, whi + WOFF_L2, wlo + WOFF_L2, b_m2, b_l2,
        Ff, fhi, flo, nullptr, D_DIM, HE_DIM);
    // fusion layer 1: G = relu(FUSED @ W_f1 + b_f1)
    mm_hmma<true, false, false, false, true, false, false>
        <<<dim3(HF_DIM / 256, mtiles), blk, DYN_SMEM>>>(
        fhi, flo, whi + WOFF_F1, wlo + WOFF_F1, nullptr, nullptr, b_f1, nullptr,
        nullptr, ghi, glo, nullptr, HF_DIM, D_DIM);
    // fusion layer 2: out = FUSED + G @ W_f2 + b_f2
    mm_hmma<false, false, true, true, false, false, false>
        <<<dim3(D_DIM / 256, mtiles), blk, DYN_SMEM>>>(
        ghi, glo, whi + WOFF_F2, wlo + WOFF_F2, nullptr, nullptr, b_f2, nullptr,
        out, nullptr, nullptr, Ff, D_DIM, HF_DIM);
}